// round 10
// baseline (speedup 1.0000x reference)
#include <cuda_runtime.h>
#include <cuda_bf16.h>
#include <cstdint>

#define NMAX 50000
#define F 128
#define DEG 32
#define L2OUT 40
#define PNLD 64            // padded pn row (128B-aligned, 3 sectors/row)

typedef __nv_bfloat16 bf16;

// Scratch (device globals — no allocation allowed).
__device__ bf16 g_fhi[NMAX * F];          // feats hi
__device__ bf16 g_flo[NMAX * F];          // feats lo (residual)
__device__ bf16 g_m1hi[NMAX * F];         // neighbor-mean (hi only)
__device__ bf16 g_w1hi[128 * 256];        // W1^T hi  [n][k]
__device__ bf16 g_w1lo[128 * 256];        // W1^T lo
__device__ bf16 g_w2hi[96 * 128];         // W2cat^T hi [n][k] (n>=80 zero)
__device__ bf16 g_w2lo[96 * 128];
__device__ float g_ps[NMAX * L2OUT];      // self projection (fp32)
__device__ bf16  g_pn[NMAX * PNLD];       // neighbor projection (bf16, padded)

// ======================== helpers ======================
__device__ __forceinline__ uint32_t smem_u32(const void* p) {
    uint32_t a;
    asm("{ .reg .u64 t; cvta.to.shared.u64 t, %1; cvt.u32.u64 %0, t; }"
        : "=r"(a) : "l"(p));
    return a;
}
__device__ __forceinline__ void cp_async16(uint32_t dst, const void* src,
                                           uint32_t srcsz) {
    asm volatile("cp.async.cg.shared.global [%0], [%1], 16, %2;"
                 :: "r"(dst), "l"(src), "r"(srcsz) : "memory");
}
__device__ __forceinline__ void cp_commit() {
    asm volatile("cp.async.commit_group;" ::: "memory");
}
template <int N_>
__device__ __forceinline__ void cp_wait() {
    asm volatile("cp.async.wait_group %0;" :: "n"(N_) : "memory");
}
__device__ __forceinline__ void ldm_x4(uint32_t& r0, uint32_t& r1,
                                       uint32_t& r2, uint32_t& r3, uint32_t a) {
    asm volatile("ldmatrix.sync.aligned.m8n8.x4.shared.b16 {%0,%1,%2,%3}, [%4];"
                 : "=r"(r0), "=r"(r1), "=r"(r2), "=r"(r3) : "r"(a));
}
__device__ __forceinline__ void mma_bf16(float* c, const uint32_t* a,
                                         const uint32_t* b) {
    asm volatile(
        "mma.sync.aligned.m16n8k16.row.col.f32.bf16.bf16.f32 "
        "{%0,%1,%2,%3}, {%4,%5,%6,%7}, {%8,%9}, {%0,%1,%2,%3};"
        : "+f"(c[0]), "+f"(c[1]), "+f"(c[2]), "+f"(c[3])
        : "r"(a[0]), "r"(a[1]), "r"(a[2]), "r"(a[3]), "r"(b[0]), "r"(b[1]));
}
__device__ __forceinline__ uint32_t bf16pair(float x, float y,
                                             float& rx, float& ry) {
    bf16 hx = __float2bfloat16(x);
    bf16 hy = __float2bfloat16(y);
    rx = x - __bfloat162float(hx);
    ry = y - __bfloat162float(hy);
    return ((uint32_t)__bfloat16_as_ushort(hy) << 16) |
           (uint32_t)__bfloat16_as_ushort(hx);
}
__device__ __forceinline__ uint32_t bf16pair_lo(float rx, float ry) {
    bf16 lx = __float2bfloat16(rx);
    bf16 ly = __float2bfloat16(ry);
    return ((uint32_t)__bfloat16_as_ushort(ly) << 16) |
           (uint32_t)__bfloat16_as_ushort(lx);
}
__device__ __forceinline__ uint32_t pack_bf16(float x, float y) {
    return ((uint32_t)__bfloat16_as_ushort(__float2bfloat16(y)) << 16) |
           (uint32_t)__bfloat16_as_ushort(__float2bfloat16(x));
}

// ---------------------------------------------------------------------------
// One-time weight prep.
// ---------------------------------------------------------------------------
__global__ __launch_bounds__(256)
void wprep(const float* __restrict__ W1, const float* __restrict__ W2,
           bf16* __restrict__ w1hi, bf16* __restrict__ w1lo,
           bf16* __restrict__ w2hi, bf16* __restrict__ w2lo)
{
    int i = blockIdx.x * 256 + threadIdx.x;
    if (i < 128 * 256) {
        int n = i >> 8, k = i & 255;
        float v = W1[(size_t)k * 128 + n];
        bf16 h = __float2bfloat16(v);
        w1hi[i] = h;
        w1lo[i] = __float2bfloat16(v - __bfloat162float(h));
    } else if (i < 128 * 256 + 96 * 128) {
        int j = i - 128 * 256;
        int n = j >> 7, k = j & 127;
        float v = 0.f;
        if (n < L2OUT)          v = W2[(size_t)k * L2OUT + n];
        else if (n < 2 * L2OUT) v = W2[(size_t)(F + k) * L2OUT + (n - L2OUT)];
        bf16 h = __float2bfloat16(v);
        w2hi[j] = h;
        w2lo[j] = __float2bfloat16(v - __bfloat162float(h));
    }
}

// ---------------------------------------------------------------------------
// feats fp32 -> hi/lo bf16.
// ---------------------------------------------------------------------------
__global__ __launch_bounds__(256)
void featprep(const float* __restrict__ src, bf16* __restrict__ hi,
              bf16* __restrict__ lo, int n4)
{
    int i = blockIdx.x * 256 + threadIdx.x;
    if (i >= n4) return;
    float4 v = reinterpret_cast<const float4*>(src)[i];
    float r0, r1, r2, r3;
    uint32_t h0 = bf16pair(v.x, v.y, r0, r1);
    uint32_t h1 = bf16pair(v.z, v.w, r2, r3);
    uint32_t l0 = bf16pair_lo(r0, r1);
    uint32_t l1 = bf16pair_lo(r2, r3);
    reinterpret_cast<uint2*>(hi)[i] = make_uint2(h0, h1);
    reinterpret_cast<uint2*>(lo)[i] = make_uint2(l0, l1);
}

// ---------------------------------------------------------------------------
// Gather-mean over bf16 feats (fp32 accumulation), emit bf16 (hi only).
// ---------------------------------------------------------------------------
__global__ __launch_bounds__(256)
void gather_mean_bf16(const bf16* __restrict__ src,
                      const int* __restrict__ neigh,
                      bf16* __restrict__ dhi, int N)
{
    int w    = (blockIdx.x * blockDim.x + threadIdx.x) >> 5;
    int lane = threadIdx.x & 31;
    if (w >= N) return;
    int myidx = neigh[w * DEG + lane];

    float4 acc = make_float4(0.f, 0.f, 0.f, 0.f);
#pragma unroll
    for (int j = 0; j < DEG; ++j) {
        int nb = __shfl_sync(0xffffffffu, myidx, j);
        uint2 u = __ldg(reinterpret_cast<const uint2*>(src + (size_t)nb * F) + lane);
        float2 a = __bfloat1622float2(*reinterpret_cast<__nv_bfloat162*>(&u.x));
        float2 b = __bfloat1622float2(*reinterpret_cast<__nv_bfloat162*>(&u.y));
        acc.x += a.x; acc.y += a.y; acc.z += b.x; acc.w += b.y;
    }
    const float s = 1.0f / (float)DEG;
    uint32_t h0 = pack_bf16(acc.x * s, acc.y * s);
    uint32_t h1 = pack_bf16(acc.z * s, acc.w * s);
    reinterpret_cast<uint2*>(dhi + (size_t)w * F)[lane] = make_uint2(h0, h1);
}

// ---------------------------------------------------------------------------
// Persistent fused GEMM. BM=64, 512 threads (16 warps = 4m x 4n, warp tile
// 16x32 stage-1 / 16x24 stage-2). Each CTA loops over row-blocks; during the
// last stage-1 chunk of block j it prefetches block j+gridDim's chunk 0, so
// prologue latency is paid once per CTA, not once per block. W2 persistent.
//   stage 1: c<2 (feats): ahi*(bhi+blo) + alo*bhi  |  c>=2 (m1): ahi*(bhi+blo)
//   stage 2: (h1hi+h1lo)*(W2hi+W2lo)
// SMEM: buf0 [0,55296), buf1 [55296,110592): {AHI 9216, ALO 9216, BHI 18432,
// BLO 18432}. H1 hi/lo overlays buf0 ([0,34816)). W2 at 110592 (2x26112).
// ---------------------------------------------------------------------------
#define LDT  72
#define LDT2 136
#define BUFSZ   55296
#define OFF_AHI 0
#define OFF_ALO 9216
#define OFF_BHI 18432
#define OFF_BLO 36864
#define H1_HI   0
#define H1_LO   17408
#define B2_HI   110592
#define B2_LO   136704
#define SM_TOT  162816

__global__ __launch_bounds__(512, 1)
void gemm_fused(const bf16* __restrict__ fhi, const bf16* __restrict__ flo,
                const bf16* __restrict__ m1hi,
                const bf16* __restrict__ w1hi, const bf16* __restrict__ w1lo,
                const bf16* __restrict__ w2hi, const bf16* __restrict__ w2lo,
                const float* __restrict__ b1,
                float* __restrict__ PS, bf16* __restrict__ PN,
                int N, int nblocks)
{
    extern __shared__ __align__(16) char smem[];
    const uint32_t sbase = smem_u32(smem);
    const int tid   = threadIdx.x;
    const int wid   = tid >> 5;
    const int lane  = tid & 31;
    const int warpM = wid >> 2;          // 0..3 (16 rows each)
    const int warpN = wid & 3;           // 0..3

    // chunk c of block blk -> buf1 if c even, buf0 if c odd
    auto load_chunk = [&](int blk, int c) {
        const bool isF = (c < 2);
        const bf16* srcHi = isF ? fhi : m1hi;
        const int kOff = (c & 1) * 64;
        const uint32_t base = sbase + (((c & 1) == 0) ? BUFSZ : 0);
        const int rowBase = blk * 64;
        {   // A tile: 64 rows x 64 halves = 512 uint4 (one per thread)
            int row = tid >> 3, h8 = tid & 7;
            int grow = rowBase + row;
            uint32_t sz = (grow < N) ? 16u : 0u;
            size_t goff = (size_t)grow * F + kOff + h8 * 8;
            uint32_t o = (uint32_t)(row * LDT + h8 * 8) * 2;
            cp_async16(base + OFF_AHI + o, srcHi + goff, sz);
            if (isF) cp_async16(base + OFF_ALO + o, flo + goff, sz);
        }
#pragma unroll
        for (int i = tid; i < 1024; i += 512) {   // B: 128 n x 8 uint4
            int n = i >> 3, h8 = i & 7;
            size_t goff = (size_t)n * 256 + c * 64 + h8 * 8;
            uint32_t o = (uint32_t)(n * LDT + h8 * 8) * 2;
            cp_async16(base + OFF_BHI + o, w1hi + goff, 16u);
            cp_async16(base + OFF_BLO + o, w1lo + goff, 16u);
        }
    };

    // ---- prologue: first block's chunk 0 in flight; W2 persistent tiles ----
    load_chunk(blockIdx.x, 0);
    cp_commit();
#pragma unroll
    for (int i = tid; i < 1536; i += 512) {
        int n = i >> 4, h8 = i & 15;
        uint4 vh = *reinterpret_cast<const uint4*>(w2hi + n * 128 + h8 * 8);
        uint4 vl = *reinterpret_cast<const uint4*>(w2lo + n * 128 + h8 * 8);
        uint32_t o = (uint32_t)(n * LDT2 + h8 * 8) * 2;
        *reinterpret_cast<uint4*>(smem + B2_HI + o) = vh;
        *reinterpret_cast<uint4*>(smem + B2_LO + o) = vl;
    }

    // ldmatrix lane-address components
    const uint32_t aRowSel = lane & 15;
    const uint32_t aKoff   = (uint32_t)(lane >> 4) << 3;
    const uint32_t bRowSel = lane & 7;
    const uint32_t bKoff4  = (uint32_t)((lane >> 3) & 3) << 3;
    const uint32_t aOff   = ((warpM * 16 + aRowSel) * LDT + aKoff) * 2;
    const uint32_t bOff4  = ((warpN * 32 + bRowSel) * LDT + bKoff4) * 2;
    const uint32_t a2Off  = ((warpM * 16 + aRowSel) * LDT2 + aKoff) * 2;
    const uint32_t b2Off4 = ((warpN * 24 + bRowSel) * LDT2 + bKoff4) * 2;
    const int g  = lane >> 2;
    const int qc = (lane & 3) * 2;

    for (int blk = blockIdx.x; blk < nblocks; blk += gridDim.x) {
        const int rowBase = blk * 64;

        float acc[4][4];
#pragma unroll
        for (int nt = 0; nt < 4; ++nt)
#pragma unroll
            for (int q = 0; q < 4; ++q) acc[nt][q] = 0.f;

        // =================== STAGE 1 (pipelined) ===================
#pragma unroll
        for (int c = 0; c < 4; ++c) {
            const bool have_next =
                (c < 3) || (blk + (int)gridDim.x < nblocks);
            if (c < 3)              load_chunk(blk, c + 1);
            else if (have_next)     load_chunk(blk + gridDim.x, 0);
            if (have_next) { cp_commit(); cp_wait<1>(); }
            else           cp_wait<0>();
            __syncthreads();

            const uint32_t base = sbase + (((c & 1) == 0) ? BUFSZ : 0);
            const bool useLo = (c < 2);
#pragma unroll
            for (int ks2 = 0; ks2 < 2; ++ks2) {
                uint32_t bhi[4][4], blo[4][4];
#pragma unroll
                for (int nt = 0; nt < 4; ++nt) {
                    uint32_t bo = base + bOff4 + nt * (8 * LDT * 2) + ks2 * 64;
                    ldm_x4(bhi[nt][0], bhi[nt][1], bhi[nt][2], bhi[nt][3],
                           bo + OFF_BHI);
                    ldm_x4(blo[nt][0], blo[nt][1], blo[nt][2], blo[nt][3],
                           bo + OFF_BLO);
                }
#pragma unroll
                for (int sub = 0; sub < 2; ++sub) {
                    const uint32_t k2 = (ks2 * 2 + sub) * 32;
                    uint32_t ahi[4], alo[4];
                    uint32_t ao = base + aOff + k2;
                    ldm_x4(ahi[0], ahi[1], ahi[2], ahi[3], ao + OFF_AHI);
                    if (useLo)
                        ldm_x4(alo[0], alo[1], alo[2], alo[3], ao + OFF_ALO);
#pragma unroll
                    for (int nt = 0; nt < 4; ++nt) {
                        mma_bf16(acc[nt], ahi, &bhi[nt][sub * 2]);
                        mma_bf16(acc[nt], ahi, &blo[nt][sub * 2]);
                        if (useLo)
                            mma_bf16(acc[nt], alo, &bhi[nt][sub * 2]);
                    }
                }
            }
            __syncthreads();
        }

        // ---- bias + relu -> h1 hi/lo into buf0 ----
#pragma unroll
        for (int nt = 0; nt < 4; ++nt) {
            int col = warpN * 32 + nt * 8 + qc;
            float bx = b1[col], by = b1[col + 1];
            int rl0 = warpM * 16 + g;
            int rl1 = rl0 + 8;
            float v0 = fmaxf(acc[nt][0] + bx, 0.f);
            float v1 = fmaxf(acc[nt][1] + by, 0.f);
            float v2 = fmaxf(acc[nt][2] + bx, 0.f);
            float v3 = fmaxf(acc[nt][3] + by, 0.f);
            float rx, ry;
            uint32_t hi0 = bf16pair(v0, v1, rx, ry);
            uint32_t lo0 = bf16pair_lo(rx, ry);
            uint32_t o0 = (uint32_t)(rl0 * LDT2 + col) * 2;
            uint32_t hi1 = bf16pair(v2, v3, rx, ry);
            uint32_t lo1 = bf16pair_lo(rx, ry);
            uint32_t o1 = (uint32_t)(rl1 * LDT2 + col) * 2;
            *reinterpret_cast<uint32_t*>(smem + H1_HI + o0) = hi0;
            *reinterpret_cast<uint32_t*>(smem + H1_LO + o0) = lo0;
            *reinterpret_cast<uint32_t*>(smem + H1_HI + o1) = hi1;
            *reinterpret_cast<uint32_t*>(smem + H1_LO + o1) = lo1;
        }
        __syncthreads();

        // =================== STAGE 2 ===================
        float acc2[3][4];
#pragma unroll
        for (int nt = 0; nt < 3; ++nt)
#pragma unroll
            for (int q = 0; q < 4; ++q) acc2[nt][q] = 0.f;

#pragma unroll
        for (int ks2 = 0; ks2 < 4; ++ks2) {
            uint32_t bhi[3][4], blo[3][4];
#pragma unroll
            for (int nt = 0; nt < 3; ++nt) {
                uint32_t bo = sbase + b2Off4 + nt * (8 * LDT2 * 2) + ks2 * 64;
                ldm_x4(bhi[nt][0], bhi[nt][1], bhi[nt][2], bhi[nt][3],
                       bo + B2_HI);
                ldm_x4(blo[nt][0], blo[nt][1], blo[nt][2], blo[nt][3],
                       bo + B2_LO);
            }
#pragma unroll
            for (int sub = 0; sub < 2; ++sub) {
                const uint32_t k2 = (ks2 * 2 + sub) * 32;
                uint32_t ahi[4], alo[4];
                uint32_t ao = sbase + a2Off + k2;
                ldm_x4(ahi[0], ahi[1], ahi[2], ahi[3], ao + H1_HI);
                ldm_x4(alo[0], alo[1], alo[2], alo[3], ao + H1_LO);
#pragma unroll
                for (int nt = 0; nt < 3; ++nt) {
                    mma_bf16(acc2[nt], ahi, &bhi[nt][sub * 2]);
                    mma_bf16(acc2[nt], ahi, &blo[nt][sub * 2]);
                    mma_bf16(acc2[nt], alo, &bhi[nt][sub * 2]);
                }
            }
        }

        // ---- stores: cols 0..39 -> PS (fp32), 40..79 -> PN (bf16 padded) ----
#pragma unroll
        for (int nt = 0; nt < 3; ++nt) {
            int col = warpN * 24 + nt * 8 + qc;
            if (col >= 2 * L2OUT) continue;
            int row0 = rowBase + warpM * 16 + g;
            int row1 = row0 + 8;
            if (col < L2OUT) {
                if (row0 < N)
                    *reinterpret_cast<float2*>(&PS[(size_t)row0 * L2OUT + col]) =
                        make_float2(acc2[nt][0], acc2[nt][1]);
                if (row1 < N)
                    *reinterpret_cast<float2*>(&PS[(size_t)row1 * L2OUT + col]) =
                        make_float2(acc2[nt][2], acc2[nt][3]);
            } else {
                int cn = col - L2OUT;
                if (row0 < N)
                    *reinterpret_cast<uint32_t*>(PN + (size_t)row0 * PNLD + cn) =
                        pack_bf16(acc2[nt][0], acc2[nt][1]);
                if (row1 < N)
                    *reinterpret_cast<uint32_t*>(PN + (size_t)row1 * PNLD + cn) =
                        pack_bf16(acc2[nt][2], acc2[nt][3]);
            }
        }
        __syncthreads();   // H1/buf0 free before next block's c1 load
    }
}

// ---------------------------------------------------------------------------
// Finalize: out[i][c] = ps[batch[i]][c] + mean_j pn[neigh[batch[i]][j]][c] + b2[c]
// ---------------------------------------------------------------------------
__global__ __launch_bounds__(256)
void finalize40(const float* __restrict__ ps, const bf16* __restrict__ pn,
                const int* __restrict__ neigh,
                const int* __restrict__ batch,
                const float* __restrict__ b2,
                float* __restrict__ out, int N)
{
    int w    = (blockIdx.x * blockDim.x + threadIdx.x) >> 5;
    int lane = threadIdx.x & 31;
    if (w >= N) return;
    int node  = batch[w];
    int myidx = neigh[node * DEG + lane];
    const bool active = lane < (L2OUT / 2);

    float ax = 0.f, ay = 0.f;
#pragma unroll
    for (int j = 0; j < DEG; ++j) {
        int nb = __shfl_sync(0xffffffffu, myidx, j);
        if (active) {
            uint32_t u = __ldg(reinterpret_cast<const uint32_t*>(
                                   pn + (size_t)nb * PNLD) + lane);
            float2 v = __bfloat1622float2(*reinterpret_cast<__nv_bfloat162*>(&u));
            ax += v.x; ay += v.y;
        }
    }
    if (active) {
        const float s = 1.0f / (float)DEG;
        float2 self = *reinterpret_cast<const float2*>(
                          ps + (size_t)node * L2OUT + lane * 2);
        float2 bb = *reinterpret_cast<const float2*>(b2 + lane * 2);
        float2 o = make_float2(self.x + ax * s + bb.x,
                               self.y + ay * s + bb.y);
        *reinterpret_cast<float2*>(out + (size_t)w * L2OUT + lane * 2) = o;
    }
}

// ---------------------------------------------------------------------------
extern "C" void kernel_launch(void* const* d_in, const int* in_sizes, int n_in,
                              void* d_out, int out_size)
{
    const float* feats = (const float*)d_in[0];
    const int*   neigh = (const int*)  d_in[1];
    const int*   batch = (const int*)  d_in[2];
    const float* W1    = (const float*)d_in[3];
    const float* b1    = (const float*)d_in[4];
    const float* W2    = (const float*)d_in[5];
    const float* b2    = (const float*)d_in[6];
    float*       out   = (float*)d_out;

    const int N = in_sizes[0] / F;   // 50000
    const int B = in_sizes[2];       // = N

    bf16 *fhi, *flo, *m1hi, *w1hi, *w1lo, *w2hi, *w2lo, *pn;
    float *ps;
    cudaGetSymbolAddress((void**)&fhi,  g_fhi);
    cudaGetSymbolAddress((void**)&flo,  g_flo);
    cudaGetSymbolAddress((void**)&m1hi, g_m1hi);
    cudaGetSymbolAddress((void**)&w1hi, g_w1hi);
    cudaGetSymbolAddress((void**)&w1lo, g_w1lo);
    cudaGetSymbolAddress((void**)&w2hi, g_w2hi);
    cudaGetSymbolAddress((void**)&w2lo, g_w2lo);
    cudaGetSymbolAddress((void**)&ps,   g_ps);
    cudaGetSymbolAddress((void**)&pn,   g_pn);

    cudaFuncSetAttribute(gemm_fused, cudaFuncAttributeMaxDynamicSharedMemorySize,
                         SM_TOT);

    const int n4 = N * F / 4;
    const int nblocks = (N + 63) / 64;
    const int grid = 152 < nblocks ? 152 : nblocks;   // GB300: 152 SMs

    wprep<<<(128 * 256 + 96 * 128 + 255) / 256, 256>>>(W1, W2, w1hi, w1lo,
                                                       w2hi, w2lo);
    featprep<<<(n4 + 255) / 256, 256>>>(feats, fhi, flo, n4);
    gather_mean_bf16<<<(N * 32 + 255) / 256, 256>>>(fhi, neigh, m1hi, N);
    gemm_fused<<<grid, 512, SM_TOT>>>(fhi, flo, m1hi, w1hi, w1lo,
                                      w2hi, w2lo, b1, ps, pn, N, nblocks);
    finalize40<<<(B * 32 + 255) / 256, 256>>>(ps, pn, neigh, batch, b2, out, B);
}

// round 11
// speedup vs baseline: 1.0669x; 1.0669x over previous
#include <cuda_runtime.h>
#include <cuda_bf16.h>
#include <cstdint>

#define NMAX 50000
#define F 128
#define DEG 32
#define L2OUT 40
#define PNLD 64            // padded pn row (128B-aligned)

typedef __nv_bfloat16 bf16;

// Scratch (device globals — no allocation allowed).
__device__ bf16 g_fhi[NMAX * F];          // feats hi
__device__ bf16 g_flo[NMAX * F];          // feats lo (residual)
__device__ bf16 g_m1hi[NMAX * F];         // neighbor-mean (hi only)
__device__ bf16 g_w1hi[128 * 256];        // W1^T hi  [n][k]
__device__ bf16 g_w1lo[128 * 256];        // W1^T lo
__device__ bf16 g_w2hi[96 * 128];         // W2cat^T hi [n][k] (n>=80 zero)
__device__ bf16 g_w2lo[96 * 128];
__device__ float g_ps[NMAX * L2OUT];      // self projection (fp32)
__device__ bf16  g_pn[NMAX * PNLD];       // neighbor projection (bf16, padded)

// ======================== helpers ======================
__device__ __forceinline__ uint32_t smem_u32(const void* p) {
    uint32_t a;
    asm("{ .reg .u64 t; cvta.to.shared.u64 t, %1; cvt.u32.u64 %0, t; }"
        : "=r"(a) : "l"(p));
    return a;
}
__device__ __forceinline__ void cp_async16(uint32_t dst, const void* src,
                                           uint32_t srcsz) {
    asm volatile("cp.async.cg.shared.global [%0], [%1], 16, %2;"
                 :: "r"(dst), "l"(src), "r"(srcsz) : "memory");
}
__device__ __forceinline__ void cp_commit() {
    asm volatile("cp.async.commit_group;" ::: "memory");
}
template <int N_>
__device__ __forceinline__ void cp_wait() {
    asm volatile("cp.async.wait_group %0;" :: "n"(N_) : "memory");
}
__device__ __forceinline__ void ldm_x4(uint32_t& r0, uint32_t& r1,
                                       uint32_t& r2, uint32_t& r3, uint32_t a) {
    asm volatile("ldmatrix.sync.aligned.m8n8.x4.shared.b16 {%0,%1,%2,%3}, [%4];"
                 : "=r"(r0), "=r"(r1), "=r"(r2), "=r"(r3) : "r"(a));
}
__device__ __forceinline__ void mma_bf16(float* c, const uint32_t* a,
                                         const uint32_t* b) {
    asm volatile(
        "mma.sync.aligned.m16n8k16.row.col.f32.bf16.bf16.f32 "
        "{%0,%1,%2,%3}, {%4,%5,%6,%7}, {%8,%9}, {%0,%1,%2,%3};"
        : "+f"(c[0]), "+f"(c[1]), "+f"(c[2]), "+f"(c[3])
        : "r"(a[0]), "r"(a[1]), "r"(a[2]), "r"(a[3]), "r"(b[0]), "r"(b[1]));
}
__device__ __forceinline__ uint32_t bf16pair(float x, float y,
                                             float& rx, float& ry) {
    bf16 hx = __float2bfloat16(x);
    bf16 hy = __float2bfloat16(y);
    rx = x - __bfloat162float(hx);
    ry = y - __bfloat162float(hy);
    return ((uint32_t)__bfloat16_as_ushort(hy) << 16) |
           (uint32_t)__bfloat16_as_ushort(hx);
}
__device__ __forceinline__ uint32_t bf16pair_lo(float rx, float ry) {
    bf16 lx = __float2bfloat16(rx);
    bf16 ly = __float2bfloat16(ry);
    return ((uint32_t)__bfloat16_as_ushort(ly) << 16) |
           (uint32_t)__bfloat16_as_ushort(lx);
}
__device__ __forceinline__ uint32_t pack_bf16(float x, float y) {
    return ((uint32_t)__bfloat16_as_ushort(__float2bfloat16(y)) << 16) |
           (uint32_t)__bfloat16_as_ushort(__float2bfloat16(x));
}

// ---------------------------------------------------------------------------
// One-time weight prep.
// ---------------------------------------------------------------------------
__global__ __launch_bounds__(256)
void wprep(const float* __restrict__ W1, const float* __restrict__ W2,
           bf16* __restrict__ w1hi, bf16* __restrict__ w1lo,
           bf16* __restrict__ w2hi, bf16* __restrict__ w2lo)
{
    int i = blockIdx.x * 256 + threadIdx.x;
    if (i < 128 * 256) {
        int n = i >> 8, k = i & 255;
        float v = W1[(size_t)k * 128 + n];
        bf16 h = __float2bfloat16(v);
        w1hi[i] = h;
        w1lo[i] = __float2bfloat16(v - __bfloat162float(h));
    } else if (i < 128 * 256 + 96 * 128) {
        int j = i - 128 * 256;
        int n = j >> 7, k = j & 127;
        float v = 0.f;
        if (n < L2OUT)          v = W2[(size_t)k * L2OUT + n];
        else if (n < 2 * L2OUT) v = W2[(size_t)(F + k) * L2OUT + (n - L2OUT)];
        bf16 h = __float2bfloat16(v);
        w2hi[j] = h;
        w2lo[j] = __float2bfloat16(v - __bfloat162float(h));
    }
}

// ---------------------------------------------------------------------------
// feats fp32 -> hi/lo bf16.
// ---------------------------------------------------------------------------
__global__ __launch_bounds__(256)
void featprep(const float* __restrict__ src, bf16* __restrict__ hi,
              bf16* __restrict__ lo, int n4)
{
    int i = blockIdx.x * 256 + threadIdx.x;
    if (i >= n4) return;
    float4 v = reinterpret_cast<const float4*>(src)[i];
    float r0, r1, r2, r3;
    uint32_t h0 = bf16pair(v.x, v.y, r0, r1);
    uint32_t h1 = bf16pair(v.z, v.w, r2, r3);
    uint32_t l0 = bf16pair_lo(r0, r1);
    uint32_t l1 = bf16pair_lo(r2, r3);
    reinterpret_cast<uint2*>(hi)[i] = make_uint2(h0, h1);
    reinterpret_cast<uint2*>(lo)[i] = make_uint2(l0, l1);
}

// ---------------------------------------------------------------------------
// Gather-mean over bf16 feats (fp32 accumulation), emit bf16 (hi only).
// ---------------------------------------------------------------------------
__global__ __launch_bounds__(256)
void gather_mean_bf16(const bf16* __restrict__ src,
                      const int* __restrict__ neigh,
                      bf16* __restrict__ dhi, int N)
{
    int w    = (blockIdx.x * blockDim.x + threadIdx.x) >> 5;
    int lane = threadIdx.x & 31;
    if (w >= N) return;
    int myidx = neigh[w * DEG + lane];

    float4 acc = make_float4(0.f, 0.f, 0.f, 0.f);
#pragma unroll
    for (int j = 0; j < DEG; ++j) {
        int nb = __shfl_sync(0xffffffffu, myidx, j);
        uint2 u = __ldg(reinterpret_cast<const uint2*>(src + (size_t)nb * F) + lane);
        float2 a = __bfloat1622float2(*reinterpret_cast<__nv_bfloat162*>(&u.x));
        float2 b = __bfloat1622float2(*reinterpret_cast<__nv_bfloat162*>(&u.y));
        acc.x += a.x; acc.y += a.y; acc.z += b.x; acc.w += b.y;
    }
    const float s = 1.0f / (float)DEG;
    uint32_t h0 = pack_bf16(acc.x * s, acc.y * s);
    uint32_t h1 = pack_bf16(acc.z * s, acc.w * s);
    reinterpret_cast<uint2*>(dhi + (size_t)w * F)[lane] = make_uint2(h0, h1);
}

// ---------------------------------------------------------------------------
// Persistent fused GEMM (R9 geometry: BM=128, 16 warps, warp tile 32x32).
// Each CTA loops blocks (stride gridDim); W2 tiles load once per CTA; at the
// last stage-1 chunk of a block, the NEXT block's chunk 0 is prefetched so
// the load prologue is exposed once per CTA, not once per wave.
//   stage 1: c<2 (feats): ahi*(bhi+blo) + alo*bhi  |  c>=2 (m1): ahi*(bhi+blo)
//   stage 2: (h1hi+h1lo)*(W2hi+W2lo)
// Buffers: chunk c -> buf(c&1) (chunk0->buf0). H1 overlays buf1 so the
// prefetched chunk 0 (buf0) survives the epilogue/stage 2.
// ---------------------------------------------------------------------------
#define LDT  72
#define LDT2 136
#define BUFSZ   73728
#define OFF_AHI 0
#define OFF_ALO 18432
#define OFF_BHI 36864
#define OFF_BLO 55296
#define H1_HI   (BUFSZ + 0)
#define H1_LO   (BUFSZ + 34816)
#define B2_HI   147456
#define B2_LO   173568
#define SM_TOT  199680

__global__ __launch_bounds__(512, 1)
void gemm_fused(const bf16* __restrict__ fhi, const bf16* __restrict__ flo,
                const bf16* __restrict__ m1hi,
                const bf16* __restrict__ w1hi, const bf16* __restrict__ w1lo,
                const bf16* __restrict__ w2hi, const bf16* __restrict__ w2lo,
                const float* __restrict__ b1,
                float* __restrict__ PS, bf16* __restrict__ PN,
                int N, int nblocks)
{
    extern __shared__ __align__(16) char smem[];
    const uint32_t sbase = smem_u32(smem);
    const int tid   = threadIdx.x;
    const int wid   = tid >> 5;
    const int lane  = tid & 31;
    const int warpM = wid >> 2;
    const int warpN = wid & 3;

    // chunk c of block blk -> buf(c&1)
    auto load_chunk = [&](int blk, int c) {
        const bool isF = (c < 2);
        const bf16* srcHi = isF ? fhi : m1hi;
        const int kOff = (c & 1) * 64;
        const uint32_t base = sbase + (c & 1) * BUFSZ;
        const int rowBase = blk * 128;
#pragma unroll
        for (int i = tid; i < 1024; i += 512) {
            int row = i >> 3, h8 = i & 7;
            int grow = rowBase + row;
            uint32_t sz = (grow < N) ? 16u : 0u;
            size_t goff = (size_t)grow * F + kOff + h8 * 8;
            uint32_t o = (uint32_t)(row * LDT + h8 * 8) * 2;
            cp_async16(base + OFF_AHI + o, srcHi + goff, sz);
            if (isF) cp_async16(base + OFF_ALO + o, flo + goff, sz);
        }
#pragma unroll
        for (int i = tid; i < 1024; i += 512) {
            int n = i >> 3, h8 = i & 7;
            size_t goff = (size_t)n * 256 + c * 64 + h8 * 8;
            uint32_t o = (uint32_t)(n * LDT + h8 * 8) * 2;
            cp_async16(base + OFF_BHI + o, w1hi + goff, 16u);
            cp_async16(base + OFF_BLO + o, w1lo + goff, 16u);
        }
    };

    // ---- prologue (once per CTA): first chunk in flight, W2 persistent ----
    load_chunk(blockIdx.x, 0);
    cp_commit();
#pragma unroll
    for (int i = tid; i < 1536; i += 512) {
        int n = i >> 4, h8 = i & 15;
        uint4 vh = *reinterpret_cast<const uint4*>(w2hi + n * 128 + h8 * 8);
        uint4 vl = *reinterpret_cast<const uint4*>(w2lo + n * 128 + h8 * 8);
        uint32_t o = (uint32_t)(n * LDT2 + h8 * 8) * 2;
        *reinterpret_cast<uint4*>(smem + B2_HI + o) = vh;
        *reinterpret_cast<uint4*>(smem + B2_LO + o) = vl;
    }

    // ldmatrix lane-address components
    const uint32_t aRowSel = lane & 15;
    const uint32_t aKoff   = (uint32_t)(lane >> 4) << 3;
    const uint32_t bRowSel = lane & 7;
    const uint32_t bKoff4  = (uint32_t)((lane >> 3) & 3) << 3;
    const uint32_t aOff   = ((warpM * 32 + aRowSel) * LDT + aKoff) * 2;
    const uint32_t bOff4  = ((warpN * 32 + bRowSel) * LDT + bKoff4) * 2;
    const uint32_t a2Off  = ((warpM * 32 + aRowSel) * LDT2 + aKoff) * 2;
    const uint32_t b2Off4 = ((warpN * 24 + bRowSel) * LDT2 + bKoff4) * 2;
    const int g  = lane >> 2;
    const int qc = (lane & 3) * 2;

    for (int blk = blockIdx.x; blk < nblocks; blk += gridDim.x) {
        const int rowBase = blk * 128;

        float acc[2][4][4];
#pragma unroll
        for (int mt = 0; mt < 2; ++mt)
#pragma unroll
            for (int nt = 0; nt < 4; ++nt)
#pragma unroll
                for (int q = 0; q < 4; ++q) acc[mt][nt][q] = 0.f;

        // =================== STAGE 1 (pipelined) ===================
#pragma unroll
        for (int c = 0; c < 4; ++c) {
            bool waited1 = true;
            if (c < 3) {
                load_chunk(blk, c + 1);
                cp_commit();
            } else if (blk + (int)gridDim.x < nblocks) {
                load_chunk(blk + gridDim.x, 0);   // cross-block prefetch
                cp_commit();
            } else {
                waited1 = false;
            }
            if (waited1) cp_wait<1>(); else cp_wait<0>();
            __syncthreads();

            const uint32_t base = sbase + (c & 1) * BUFSZ;
            const bool useLo = (c < 2);
#pragma unroll
            for (int ks2 = 0; ks2 < 2; ++ks2) {
                uint32_t bhi[4][4], blo[4][4];
#pragma unroll
                for (int nt = 0; nt < 4; ++nt) {
                    uint32_t bo = base + bOff4 + nt * (8 * LDT * 2) + ks2 * 64;
                    ldm_x4(bhi[nt][0], bhi[nt][1], bhi[nt][2], bhi[nt][3],
                           bo + OFF_BHI);
                    ldm_x4(blo[nt][0], blo[nt][1], blo[nt][2], blo[nt][3],
                           bo + OFF_BLO);
                }
#pragma unroll
                for (int sub = 0; sub < 2; ++sub) {
                    const uint32_t k2 = (ks2 * 2 + sub) * 32;
                    uint32_t ahi[2][4], alo[2][4];
#pragma unroll
                    for (int mt = 0; mt < 2; ++mt) {
                        uint32_t ao = base + aOff + mt * (16 * LDT * 2) + k2;
                        ldm_x4(ahi[mt][0], ahi[mt][1], ahi[mt][2], ahi[mt][3],
                               ao + OFF_AHI);
                        if (useLo)
                            ldm_x4(alo[mt][0], alo[mt][1], alo[mt][2],
                                   alo[mt][3], ao + OFF_ALO);
                    }
#pragma unroll
                    for (int mt = 0; mt < 2; ++mt)
#pragma unroll
                        for (int nt = 0; nt < 4; ++nt) {
                            mma_bf16(acc[mt][nt], ahi[mt], &bhi[nt][sub * 2]);
                            mma_bf16(acc[mt][nt], ahi[mt], &blo[nt][sub * 2]);
                            if (useLo)
                                mma_bf16(acc[mt][nt], alo[mt],
                                         &bhi[nt][sub * 2]);
                        }
                }
            }
            __syncthreads();
        }

        // ---- bias + relu -> h1 hi/lo into buf1 overlay ----
#pragma unroll
        for (int mt = 0; mt < 2; ++mt) {
#pragma unroll
            for (int nt = 0; nt < 4; ++nt) {
                int col = warpN * 32 + nt * 8 + qc;
                float bx = b1[col], by = b1[col + 1];
                int rl0 = warpM * 32 + mt * 16 + g;
                int rl1 = rl0 + 8;
                float v0 = fmaxf(acc[mt][nt][0] + bx, 0.f);
                float v1 = fmaxf(acc[mt][nt][1] + by, 0.f);
                float v2 = fmaxf(acc[mt][nt][2] + bx, 0.f);
                float v3 = fmaxf(acc[mt][nt][3] + by, 0.f);
                float rx, ry;
                uint32_t hi0 = bf16pair(v0, v1, rx, ry);
                uint32_t lo0 = bf16pair_lo(rx, ry);
                uint32_t o0 = (uint32_t)(rl0 * LDT2 + col) * 2;
                uint32_t hi1 = bf16pair(v2, v3, rx, ry);
                uint32_t lo1 = bf16pair_lo(rx, ry);
                uint32_t o1 = (uint32_t)(rl1 * LDT2 + col) * 2;
                *reinterpret_cast<uint32_t*>(smem + H1_HI + o0) = hi0;
                *reinterpret_cast<uint32_t*>(smem + H1_LO + o0) = lo0;
                *reinterpret_cast<uint32_t*>(smem + H1_HI + o1) = hi1;
                *reinterpret_cast<uint32_t*>(smem + H1_LO + o1) = lo1;
            }
        }
        __syncthreads();

        // =================== STAGE 2 ===================
        float acc2[2][3][4];
#pragma unroll
        for (int mt = 0; mt < 2; ++mt)
#pragma unroll
            for (int nt = 0; nt < 3; ++nt)
#pragma unroll
                for (int q = 0; q < 4; ++q) acc2[mt][nt][q] = 0.f;

#pragma unroll
        for (int ks2 = 0; ks2 < 4; ++ks2) {
            uint32_t bhi[3][4], blo[3][4];
#pragma unroll
            for (int nt = 0; nt < 3; ++nt) {
                uint32_t bo = sbase + b2Off4 + nt * (8 * LDT2 * 2) + ks2 * 64;
                ldm_x4(bhi[nt][0], bhi[nt][1], bhi[nt][2], bhi[nt][3],
                       bo + B2_HI);
                ldm_x4(blo[nt][0], blo[nt][1], blo[nt][2], blo[nt][3],
                       bo + B2_LO);
            }
#pragma unroll
            for (int sub = 0; sub < 2; ++sub) {
                const uint32_t k2 = (ks2 * 2 + sub) * 32;
                uint32_t ahi[2][4], alo[2][4];
#pragma unroll
                for (int mt = 0; mt < 2; ++mt) {
                    uint32_t ao = sbase + a2Off + mt * (16 * LDT2 * 2) + k2;
                    ldm_x4(ahi[mt][0], ahi[mt][1], ahi[mt][2], ahi[mt][3],
                           ao + H1_HI);
                    ldm_x4(alo[mt][0], alo[mt][1], alo[mt][2], alo[mt][3],
                           ao + H1_LO);
                }
#pragma unroll
                for (int mt = 0; mt < 2; ++mt)
#pragma unroll
                    for (int nt = 0; nt < 3; ++nt) {
                        mma_bf16(acc2[mt][nt], ahi[mt], &bhi[nt][sub * 2]);
                        mma_bf16(acc2[mt][nt], ahi[mt], &blo[nt][sub * 2]);
                        mma_bf16(acc2[mt][nt], alo[mt], &bhi[nt][sub * 2]);
                    }
            }
        }

        // ---- stores: cols 0..39 -> PS (fp32), 40..79 -> PN (bf16) ----
#pragma unroll
        for (int mt = 0; mt < 2; ++mt) {
#pragma unroll
            for (int nt = 0; nt < 3; ++nt) {
                int col = warpN * 24 + nt * 8 + qc;
                if (col >= 2 * L2OUT) continue;
                int row0 = rowBase + warpM * 32 + mt * 16 + g;
                int row1 = row0 + 8;
                if (col < L2OUT) {
                    if (row0 < N)
                        *reinterpret_cast<float2*>(&PS[(size_t)row0 * L2OUT + col]) =
                            make_float2(acc2[mt][nt][0], acc2[mt][nt][1]);
                    if (row1 < N)
                        *reinterpret_cast<float2*>(&PS[(size_t)row1 * L2OUT + col]) =
                            make_float2(acc2[mt][nt][2], acc2[mt][nt][3]);
                } else {
                    int cn = col - L2OUT;
                    if (row0 < N)
                        *reinterpret_cast<uint32_t*>(PN + (size_t)row0 * PNLD + cn) =
                            pack_bf16(acc2[mt][nt][0], acc2[mt][nt][1]);
                    if (row1 < N)
                        *reinterpret_cast<uint32_t*>(PN + (size_t)row1 * PNLD + cn) =
                            pack_bf16(acc2[mt][nt][2], acc2[mt][nt][3]);
                }
            }
        }
        __syncthreads();   // buf1/H1 must be free before next block's c=1 load
    }
}

// ---------------------------------------------------------------------------
// Finalize: out[i][c] = ps[batch[i]][c] + mean_j pn[neigh[batch[i]][j]][c] + b2[c]
// ---------------------------------------------------------------------------
__global__ __launch_bounds__(256)
void finalize40(const float* __restrict__ ps, const bf16* __restrict__ pn,
                const int* __restrict__ neigh,
                const int* __restrict__ batch,
                const float* __restrict__ b2,
                float* __restrict__ out, int N)
{
    int w    = (blockIdx.x * blockDim.x + threadIdx.x) >> 5;
    int lane = threadIdx.x & 31;
    if (w >= N) return;
    int node  = batch[w];
    int myidx = neigh[node * DEG + lane];
    const bool active = lane < (L2OUT / 2);

    float ax = 0.f, ay = 0.f;
#pragma unroll
    for (int j = 0; j < DEG; ++j) {
        int nb = __shfl_sync(0xffffffffu, myidx, j);
        if (active) {
            uint32_t u = __ldg(reinterpret_cast<const uint32_t*>(
                                   pn + (size_t)nb * PNLD) + lane);
            float2 v = __bfloat1622float2(*reinterpret_cast<__nv_bfloat162*>(&u));
            ax += v.x; ay += v.y;
        }
    }
    if (active) {
        const float s = 1.0f / (float)DEG;
        float2 self = *reinterpret_cast<const float2*>(
                          ps + (size_t)node * L2OUT + lane * 2);
        float2 bb = *reinterpret_cast<const float2*>(b2 + lane * 2);
        float2 o = make_float2(self.x + ax * s + bb.x,
                               self.y + ay * s + bb.y);
        *reinterpret_cast<float2*>(out + (size_t)w * L2OUT + lane * 2) = o;
    }
}

// ---------------------------------------------------------------------------
extern "C" void kernel_launch(void* const* d_in, const int* in_sizes, int n_in,
                              void* d_out, int out_size)
{
    const float* feats = (const float*)d_in[0];
    const int*   neigh = (const int*)  d_in[1];
    const int*   batch = (const int*)  d_in[2];
    const float* W1    = (const float*)d_in[3];
    const float* b1    = (const float*)d_in[4];
    const float* W2    = (const float*)d_in[5];
    const float* b2    = (const float*)d_in[6];
    float*       out   = (float*)d_out;

    const int N = in_sizes[0] / F;   // 50000
    const int B = in_sizes[2];       // = N

    bf16 *fhi, *flo, *m1hi, *w1hi, *w1lo, *w2hi, *w2lo, *pn;
    float *ps;
    cudaGetSymbolAddress((void**)&fhi,  g_fhi);
    cudaGetSymbolAddress((void**)&flo,  g_flo);
    cudaGetSymbolAddress((void**)&m1hi, g_m1hi);
    cudaGetSymbolAddress((void**)&w1hi, g_w1hi);
    cudaGetSymbolAddress((void**)&w1lo, g_w1lo);
    cudaGetSymbolAddress((void**)&w2hi, g_w2hi);
    cudaGetSymbolAddress((void**)&w2lo, g_w2lo);
    cudaGetSymbolAddress((void**)&ps,   g_ps);
    cudaGetSymbolAddress((void**)&pn,   g_pn);

    cudaFuncSetAttribute(gemm_fused, cudaFuncAttributeMaxDynamicSharedMemorySize,
                         SM_TOT);

    const int n4 = N * F / 4;
    const int nblocks = (N + 127) / 128;              // 391
    const int grid = 152 < nblocks ? 152 : nblocks;   // GB300: 152 SMs

    wprep<<<(128 * 256 + 96 * 128 + 255) / 256, 256>>>(W1, W2, w1hi, w1lo,
                                                       w2hi, w2lo);
    featprep<<<(n4 + 255) / 256, 256>>>(feats, fhi, flo, n4);
    gather_mean_bf16<<<(N * 32 + 255) / 256, 256>>>(fhi, neigh, m1hi, N);
    gemm_fused<<<grid, 512, SM_TOT>>>(fhi, flo, m1hi, w1hi, w1lo,
                                      w2hi, w2lo, b1, ps, pn, N, nblocks);
    finalize40<<<(B * 32 + 255) / 256, 256>>>(ps, pn, neigh, batch, b2, out, B);
}